// round 15
// baseline (speedup 1.0000x reference)
#include <cuda_runtime.h>
#include <cuda_bf16.h>
#include <cstdint>

#define B_  2
#define L_  2048
#define D_  1024
#define H_  16
#define HD_ 64
#define M_  (B_ * L_)
#define NBH (B_ * H_)   // 32
#define KT_ (L_ / 64)   // 32 k-tiles per row in logits (64-col tiles)

// ---------------------------------------------------------------------------
// Scratch (device globals)
// ---------------------------------------------------------------------------
__device__ __nv_bfloat16 g_inh[M_ * D_], g_inl[M_ * D_];
__device__ __nv_bfloat16 g_wth[4][D_ * D_], g_wtl[4][D_ * D_];
__device__ __nv_bfloat16 g_qh[B_ * H_ * L_ * HD_], g_ql[B_ * H_ * L_ * HD_];
__device__ __nv_bfloat16 g_kh[B_ * H_ * L_ * HD_], g_kl[B_ * H_ * L_ * HD_];
__device__ __nv_bfloat16 g_vh[B_ * H_ * L_ * HD_], g_vl[B_ * H_ * L_ * HD_];
__device__ __nv_bfloat16 g_xh[M_ * D_], g_xl[M_ * D_];
__device__ float g_pmax[NBH * L_ * KT_];   // per-64col-tile row max
__device__ float g_psum[NBH * L_ * KT_];   // UNSHIFTED per-tile sum of exp(v)

__device__ __forceinline__ uint32_t smem_u32(const void* p) {
    uint32_t a;
    asm("{ .reg .u64 t; cvta.to.shared.u64 t, %1; cvt.u32.u64 %0, t; }"
        : "=r"(a) : "l"(p));
    return a;
}

__device__ __forceinline__ uint32_t sw128(uint32_t off) {
    return off ^ ((off >> 3) & 0x70);
}

__device__ __forceinline__ uint32_t pack_bf2(float a, float b) {
    return (uint32_t)__bfloat16_as_ushort(__float2bfloat16(a))
         | ((uint32_t)__bfloat16_as_ushort(__float2bfloat16(b)) << 16);
}

#define LDSM_X4(r0,r1,r2,r3,addr) \
    asm volatile("ldmatrix.sync.aligned.m8n8.x4.shared.b16 {%0,%1,%2,%3}, [%4];" \
        : "=r"(r0), "=r"(r1), "=r"(r2), "=r"(r3) : "r"(addr))

#define LDSM_X2(r0,r1,addr) \
    asm volatile("ldmatrix.sync.aligned.m8n8.x2.shared.b16 {%0,%1}, [%2];" \
        : "=r"(r0), "=r"(r1) : "r"(addr))

#define LDSM_X2T(r0,r1,addr) \
    asm volatile("ldmatrix.sync.aligned.m8n8.x2.trans.shared.b16 {%0,%1}, [%2];" \
        : "=r"(r0), "=r"(r1) : "r"(addr))

#define MMA16816(acc, af, bf) \
    asm volatile("mma.sync.aligned.m16n8k16.row.col.f32.bf16.bf16.f32 " \
        "{%0,%1,%2,%3}, {%4,%5,%6,%7}, {%8,%9}, {%0,%1,%2,%3};" \
        : "+f"((acc)[0]), "+f"((acc)[1]), "+f"((acc)[2]), "+f"((acc)[3]) \
        : "r"((af)[0]), "r"((af)[1]), "r"((af)[2]), "r"((af)[3]), \
          "r"((bf)[0]), "r"((bf)[1]))

#define CP16(dst_u32, src_ptr) \
    asm volatile("cp.async.cg.shared.global [%0], [%1], 16;" \
        :: "r"(dst_u32), "l"(src_ptr))
#define CP_COMMIT() asm volatile("cp.async.commit_group;" ::: "memory")
#define CP_WAIT0()  asm volatile("cp.async.wait_group 0;" ::: "memory")
#define CP_WAIT1()  asm volatile("cp.async.wait_group 1;" ::: "memory")

// ---------------------------------------------------------------------------
// Prep kernels
// ---------------------------------------------------------------------------
__global__ void split_x(const float* __restrict__ X)
{
    int i = (blockIdx.x * 256 + threadIdx.x) * 4;
    float4 v = *(const float4*)(X + i);
    float h0 = __bfloat162float(__float2bfloat16(v.x));
    float h1 = __bfloat162float(__float2bfloat16(v.y));
    float h2 = __bfloat162float(__float2bfloat16(v.z));
    float h3 = __bfloat162float(__float2bfloat16(v.w));
    *(uint2*)(g_inh + i) = make_uint2(pack_bf2(v.x, v.y), pack_bf2(v.z, v.w));
    *(uint2*)(g_inl + i) = make_uint2(pack_bf2(v.x - h0, v.y - h1), pack_bf2(v.z - h2, v.w - h3));
}

__global__ void split_wt(const float* __restrict__ W0, const float* __restrict__ W1,
                         const float* __restrict__ W2, const float* __restrict__ W3)
{
    __shared__ float ts[64][65];
    int widx = blockIdx.z;
    const float* W = (widx == 0) ? W0 : (widx == 1) ? W1 : (widx == 2) ? W2 : W3;
    int tid = threadIdx.x;
    int r0 = blockIdx.x * 64;
    int c0 = blockIdx.y * 64;

    #pragma unroll
    for (int i = 0; i < 4; i++) {
        int u = tid + i * 256;
        int row = u >> 4, c4 = (u & 15) * 4;
        float4 v = *(const float4*)(W + (size_t)(r0 + row) * D_ + c0 + c4);
        ts[row][c4+0] = v.x; ts[row][c4+1] = v.y;
        ts[row][c4+2] = v.z; ts[row][c4+3] = v.w;
    }
    __syncthreads();

    __nv_bfloat16* dh = g_wth[widx];
    __nv_bfloat16* dl = g_wtl[widx];
    #pragma unroll
    for (int i = 0; i < 4; i++) {
        int u = tid + i * 256;
        int nrow = u >> 4, k4 = (u & 15) * 4;
        float v0 = ts[k4+0][nrow], v1 = ts[k4+1][nrow];
        float v2 = ts[k4+2][nrow], v3 = ts[k4+3][nrow];
        float h0 = __bfloat162float(__float2bfloat16(v0));
        float h1 = __bfloat162float(__float2bfloat16(v1));
        float h2 = __bfloat162float(__float2bfloat16(v2));
        float h3 = __bfloat162float(__float2bfloat16(v3));
        size_t off = (size_t)(c0 + nrow) * D_ + r0 + k4;
        *(uint2*)(dh + off) = make_uint2(pack_bf2(v0, v1), pack_bf2(v2, v3));
        *(uint2*)(dl + off) = make_uint2(pack_bf2(v0-h0, v1-h1), pack_bf2(v2-h2, v3-h3));
    }
}

// ---------------------------------------------------------------------------
// Shared projection body: 128m x 64n tile, 2 CTAs/SM.
// Buffer (48KB): Xh@0 16K | Xl@16K | Wh@32K 8K | Wl@40K 8K ; x2 buffers.
// 8 warps (4m x 2n), 32x32 warp tiles. 3-pass hi*hi / hi*lo / lo*hi.
// ---------------------------------------------------------------------------
#define PJ_BUF  49152
#define PJ_SMEM (2 * PJ_BUF + 1024)

__device__ __forceinline__ void proj_body(
    char* smem_raw,
    const __nv_bfloat16* __restrict__ Xh, const __nv_bfloat16* __restrict__ Xl,
    const __nv_bfloat16* __restrict__ Wth, const __nv_bfloat16* __restrict__ Wtl,
    const float* __restrict__ bias, float* __restrict__ Yout,
    int mode, int n0, int m0)
{
    uint32_t raw = smem_u32(smem_raw);
    uint32_t base = (raw + 1023u) & ~1023u;

    int tid = threadIdx.x;
    int wid = tid >> 5, lane = tid & 31;
    int wm = wid >> 1;      // 0..3 : 32 m-rows
    int wn = wid & 1;       // 0..1 : 32 n-cols

    float acc[2][4][4] = {};

    int a_row_l = lane & 15;
    int a_cb_l  = (lane >> 4) << 4;
    int b_row_l = lane & 7;
    int b_cb_l  = ((lane >> 3) & 1) << 4;

    auto stage = [&](int kc, int buf) {
        uint32_t bb = base + (uint32_t)buf * PJ_BUF;
        int k0 = kc * 64;
        // X: 128 rows x 128B (hi+lo)
        #pragma unroll
        for (int i = 0; i < 4; i++) {
            int u = tid + i * 256;
            int row = u >> 3, unit = u & 7;
            uint32_t dst = sw128((uint32_t)(row * 128 + unit * 16));
            size_t xoff = (size_t)(m0 + row) * D_ + k0 + unit * 8;
            CP16(bb + dst,         Xh + xoff);
            CP16(bb + 16384 + dst, Xl + xoff);
        }
        // W: 64 rows x 128B (hi+lo)
        #pragma unroll
        for (int i = 0; i < 2; i++) {
            int u = tid + i * 256;
            int row = u >> 3, unit = u & 7;
            uint32_t dst = sw128((uint32_t)(row * 128 + unit * 16));
            size_t woff = (size_t)(n0 + row) * D_ + k0 + unit * 8;
            CP16(bb + 32768 + dst, Wth + woff);
            CP16(bb + 40960 + dst, Wtl + woff);
        }
        CP_COMMIT();
    };

    stage(0, 0);

    for (int kc = 0; kc < 16; kc++) {
        CP_WAIT0();
        __syncthreads();
        if (kc + 1 < 16) stage(kc + 1, (kc + 1) & 1);

        uint32_t bb = base + (uint32_t)(kc & 1) * PJ_BUF;

        #pragma unroll
        for (int pass = 0; pass < 3; pass++) {
            uint32_t aBase = bb + ((pass == 2) ? 16384 : 0);
            uint32_t bBase = bb + ((pass == 1) ? 40960 : 32768);

            #pragma unroll
            for (int ks = 0; ks < 4; ks++) {
                uint32_t a[2][4];
                #pragma unroll
                for (int mf = 0; mf < 2; mf++) {
                    int row = wm * 32 + mf * 16 + a_row_l;
                    uint32_t addr = aBase + sw128((uint32_t)(row * 128 + ks * 32 + a_cb_l));
                    LDSM_X4(a[mf][0], a[mf][1], a[mf][2], a[mf][3], addr);
                }
                uint32_t bf[4][2];
                #pragma unroll
                for (int nf = 0; nf < 4; nf++) {
                    int row = wn * 32 + nf * 8 + b_row_l;
                    uint32_t addr = bBase + sw128((uint32_t)(row * 128 + ks * 32 + b_cb_l));
                    LDSM_X2(bf[nf][0], bf[nf][1], addr);
                }
                #pragma unroll
                for (int mf = 0; mf < 2; mf++)
                    #pragma unroll
                    for (int nf = 0; nf < 4; nf++)
                        MMA16816(acc[mf][nf], a[mf], bf[nf]);
            }
        }
        __syncthreads();
    }

    int r0 = lane >> 2;
    int c0 = (lane & 3) * 2;
    __nv_bfloat16* dsth = (mode == 0) ? g_qh : (mode == 1) ? g_kh : g_vh;
    __nv_bfloat16* dstl = (mode == 0) ? g_ql : (mode == 1) ? g_kl : g_vl;

    #pragma unroll
    for (int mf = 0; mf < 2; mf++) {
        #pragma unroll
        for (int e2 = 0; e2 < 2; e2++) {
            int r = m0 + wm * 32 + mf * 16 + r0 + e2 * 8;
            #pragma unroll
            for (int nf = 0; nf < 4; nf++) {
                int c = n0 + wn * 32 + nf * 8 + c0;
                float v0 = acc[mf][nf][e2*2+0] + bias[c];
                float v1 = acc[mf][nf][e2*2+1] + bias[c+1];
                if (mode < 3) {
                    int b = r >> 11, l = r & 2047;
                    int h = c >> 6, hd = c & 63;
                    size_t idx = (((size_t)(b * H_ + h)) * L_ + l) * HD_ + hd;
                    float h0 = __bfloat162float(__float2bfloat16(v0));
                    float h1 = __bfloat162float(__float2bfloat16(v1));
                    *(uint32_t*)(dsth + idx) = pack_bf2(v0, v1);
                    *(uint32_t*)(dstl + idx) = pack_bf2(v0 - h0, v1 - h1);
                } else {
                    *(float2*)(Yout + (size_t)r * D_ + c) = make_float2(v0, v1);
                }
            }
        }
    }
}

__global__ void __launch_bounds__(256, 2)
qkv_mma(const __nv_bfloat16* __restrict__ Xh, const __nv_bfloat16* __restrict__ Xl,
        const __nv_bfloat16* __restrict__ Whb, const __nv_bfloat16* __restrict__ Wlb,
        const float* __restrict__ bq, const float* __restrict__ bk,
        const float* __restrict__ bv)
{
    extern __shared__ char smem_raw[];
    int m = blockIdx.z;
    const float* bias = (m == 0) ? bq : (m == 1) ? bk : bv;
    proj_body(smem_raw, Xh, Xl,
              Whb + (size_t)m * D_ * D_, Wlb + (size_t)m * D_ * D_,
              bias, nullptr, m, blockIdx.x * 64, blockIdx.y * 128);
}

__global__ void __launch_bounds__(256, 2)
oproj_mma(const __nv_bfloat16* __restrict__ Xh, const __nv_bfloat16* __restrict__ Xl,
          const __nv_bfloat16* __restrict__ Wth, const __nv_bfloat16* __restrict__ Wtl,
          const float* __restrict__ bias, float* __restrict__ Yout)
{
    extern __shared__ char smem_raw[];
    proj_body(smem_raw, Xh, Xl, Wth, Wtl, bias, Yout, 3,
              blockIdx.x * 64, blockIdx.y * 128);
}

// ---------------------------------------------------------------------------
// Logits (unchanged from R13): 128q x 64k tiles, 2 CTAs/SM.
// ---------------------------------------------------------------------------
#define LGQH  0
#define LGQL  16384
#define LGKH  32768
#define LGKL  40960
#define LGB_OFF 49152
#define LGB_ROW 272                        // 64 f32 + 16B pad
#define LG_SMEM (LGB_OFF + 128 * LGB_ROW + 1024)   // ~84.5 KB

__global__ void __launch_bounds__(256, 2)
logits_mma(const float* __restrict__ abias, float* __restrict__ attn)
{
    extern __shared__ char smem_raw[];
    uint32_t raw = smem_u32(smem_raw);
    uint32_t base = (raw + 1023u) & ~1023u;
    char* smem = smem_raw + (base - raw);

    int tid  = threadIdx.x;
    int wid  = tid >> 5;
    int lane = tid & 31;
    int bh = blockIdx.z;
    int q0 = blockIdx.y * 128;
    int k0 = blockIdx.x * 64;
    int b  = bh >> 4;

    {
        const char* sQh = (const char*)(g_qh + ((size_t)bh * L_ + q0) * HD_);
        const char* sQl = (const char*)(g_ql + ((size_t)bh * L_ + q0) * HD_);
        const char* sKh = (const char*)(g_kh + ((size_t)bh * L_ + k0) * HD_);
        const char* sKl = (const char*)(g_kl + ((size_t)bh * L_ + k0) * HD_);
        #pragma unroll
        for (int u = 0; u < 4; u++) {
            uint32_t off = (uint32_t)(tid + u * 256) * 16u;
            uint32_t sw = sw128(off);
            CP16(base + LGQH + sw, sQh + off);
            CP16(base + LGQL + sw, sQl + off);
        }
        #pragma unroll
        for (int u = 0; u < 2; u++) {
            uint32_t off = (uint32_t)(tid + u * 256) * 16u;
            uint32_t sw = sw128(off);
            CP16(base + LGKH + sw, sKh + off);
            CP16(base + LGKL + sw, sKl + off);
        }
    }
    CP_COMMIT();
    #pragma unroll
    for (int i = 0; i < 8; i++) {
        int u = tid + i * 256;
        int row = u >> 4, unit = u & 15;
        CP16(base + LGB_OFF + row * LGB_ROW + unit * 16,
             abias + ((size_t)b * L_ + q0 + row) * L_ + k0 + unit * 4);
    }
    CP_COMMIT();

    CP_WAIT1();
    __syncthreads();

    int wm = wid >> 1;
    int wn = wid & 1;

    float acc[2][4][4] = {};

    int a_row_l = lane & 15;
    int a_cb_l  = (lane >> 4) << 4;
    int b_row_l = lane & 7;
    int b_cb_l  = ((lane >> 3) & 1) << 4;

    #pragma unroll
    for (int pass = 0; pass < 3; pass++) {
        uint32_t aBase = base + ((pass == 2) ? LGQL : LGQH);
        uint32_t bBase = base + ((pass == 1) ? LGKL : LGKH);

        #pragma unroll
        for (int ks = 0; ks < 4; ks++) {
            uint32_t a[2][4];
            #pragma unroll
            for (int mf = 0; mf < 2; mf++) {
                int row = wm * 32 + mf * 16 + a_row_l;
                uint32_t addr = aBase + sw128((uint32_t)(row * 128 + ks * 32 + a_cb_l));
                LDSM_X4(a[mf][0], a[mf][1], a[mf][2], a[mf][3], addr);
            }
            uint32_t bf[4][2];
            #pragma unroll
            for (int nf = 0; nf < 4; nf++) {
                int row = wn * 32 + nf * 8 + b_row_l;
                uint32_t addr = bBase + sw128((uint32_t)(row * 128 + ks * 32 + b_cb_l));
                LDSM_X2(bf[nf][0], bf[nf][1], addr);
            }
            #pragma unroll
            for (int mf = 0; mf < 2; mf++)
                #pragma unroll
                for (int nf = 0; nf < 4; nf++)
                    MMA16816(acc[mf][nf], a[mf], bf[nf]);
        }
    }

    CP_WAIT0();
    __syncthreads();

    float* smax = (float*)smem;
    float* ssum = smax + 256;
    const float* biasS = (const float*)(smem + LGB_OFF);

    size_t attn_base = (size_t)bh * L_ * L_;
    int r0 = lane >> 2;
    int c0 = (lane & 3) * 2;

    #pragma unroll
    for (int mf = 0; mf < 2; mf++) {
        #pragma unroll
        for (int e2 = 0; e2 < 2; e2++) {
            int rw = wm * 32 + mf * 16 + e2 * 8 + r0;
            const float* brow = biasS + rw * (LGB_ROW / 4);
            float* orow = attn + attn_base + (size_t)(q0 + rw) * L_ + k0;
            float rm = -3.4e38f, s = 0.f;
            #pragma unroll
            for (int nf = 0; nf < 4; nf++) {
                int kl = wn * 32 + nf * 8 + c0;
                float v0 = acc[mf][nf][e2*2+0] * 0.125f + brow[kl];
                float v1 = acc[mf][nf][e2*2+1] * 0.125f + brow[kl+1];
                *(float2*)(orow + kl) = make_float2(v0, v1);
                rm = fmaxf(rm, fmaxf(v0, v1));
                s += __expf(v0) + __expf(v1);
            }
            rm = fmaxf(rm, __shfl_xor_sync(~0u, rm, 1));
            rm = fmaxf(rm, __shfl_xor_sync(~0u, rm, 2));
            s += __shfl_xor_sync(~0u, s, 1);
            s += __shfl_xor_sync(~0u, s, 2);
            if ((lane & 3) == 0) {
                smax[rw * 2 + wn] = rm;
                ssum[rw * 2 + wn] = s;
            }
        }
    }
    __syncthreads();
    if (tid < 128) {
        float tm = fmaxf(smax[tid*2+0], smax[tid*2+1]);
        float s  = ssum[tid*2+0] + ssum[tid*2+1];
        size_t sidx = ((size_t)bh * L_ + q0 + tid) * KT_ + blockIdx.x;
        g_pmax[sidx] = tm;
        g_psum[sidx] = s;
    }
}

// ---------------------------------------------------------------------------
// av_fused (unchanged from R13): 64-q-row CTAs, 2 CTAs/SM.
// ---------------------------------------------------------------------------
#define AV_BUF  32768
#define AV_SMEM (2 * AV_BUF + 1024)

__global__ void __launch_bounds__(256, 2)
av_fused(float* __restrict__ attn)
{
    extern __shared__ char smem_raw[];
    uint32_t raw = smem_u32(smem_raw);
    uint32_t base = (raw + 1023u) & ~1023u;
    char* smem = smem_raw + (base - raw);

    float* s_m  = (float*)(smem + 2 * AV_BUF);   // [64]
    float* s_ri = s_m + 64;                      // [64]

    int tid = threadIdx.x;
    int wid = tid >> 5, lane = tid & 31;
    int bh = blockIdx.y;
    int q0 = blockIdx.x * 64;
    int wm = wid >> 1;
    int wn = wid & 1;

    float* A = attn + (size_t)bh * L_ * L_;
    const __nv_bfloat16* Vh = g_vh + (size_t)bh * L_ * HD_;
    const __nv_bfloat16* Vl = g_vl + (size_t)bh * L_ * HD_;

    if (tid < 64) {
        size_t rowi = (size_t)bh * L_ + q0 + tid;
        const float* pm = g_pmax + rowi * KT_;
        const float* ps = g_psum + rowi * KT_;
        float M = -3.4e38f;
        #pragma unroll 8
        for (int t = 0; t < KT_; t++) M = fmaxf(M, pm[t]);
        float S = 0.f;
        #pragma unroll 8
        for (int t = 0; t < KT_; t++) S += ps[t];
        s_m[tid]  = M;
        s_ri[tid] = __expf(M) / S;
    }

    int st_row[4], st_f4[4];
    #pragma unroll
    for (int i = 0; i < 4; i++) {
        int u = tid + i * 256;
        st_row[i] = u >> 4;
        st_f4[i]  = (u & 15) * 4;
    }

    auto issueV = [&](int kc, int buf) {
        uint32_t bb = base + (uint32_t)buf * AV_BUF;
        int k0 = kc * 64;
        #pragma unroll
        for (int i = 0; i < 2; i++) {
            int u = tid + i * 256;
            int row = u >> 3, unit = u & 7;
            uint32_t dst = sw128((uint32_t)(row * 128 + unit * 16));
            size_t off = (size_t)(k0 + row) * HD_ + unit * 8;
            CP16(bb + 16384 + dst, Vh + off);
            CP16(bb + 24576 + dst, Vl + off);
        }
        CP_COMMIT();
    };

    float4 apf[4];
    auto loadA = [&](int kc) {
        int k0 = kc * 64;
        #pragma unroll
        for (int i = 0; i < 4; i++)
            apf[i] = *(const float4*)(A + (size_t)(q0 + st_row[i]) * L_ + k0 + st_f4[i]);
    };

    auto xformA = [&](int kc, int buf) {
        char* bb = smem + buf * AV_BUF;
        int k0 = kc * 64;
        #pragma unroll
        for (int i = 0; i < 4; i++) {
            int row = st_row[i], f4 = st_f4[i];
            float m = s_m[row], ri = s_ri[row];
            float4 t = apf[i];
            t.x = __expf(t.x - m) * ri;
            t.y = __expf(t.y - m) * ri;
            t.z = __expf(t.z - m) * ri;
            t.w = __expf(t.w - m) * ri;
            *(float4*)(A + (size_t)(q0 + row) * L_ + k0 + f4) = t;
            float h0 = __bfloat162float(__float2bfloat16(t.x));
            float h1 = __bfloat162float(__float2bfloat16(t.y));
            float h2 = __bfloat162float(__float2bfloat16(t.z));
            float h3 = __bfloat162float(__float2bfloat16(t.w));
            uint32_t so = sw128((uint32_t)(row * 128 + f4 * 2));
            *(uint2*)(bb + so)        = make_uint2(pack_bf2(t.x, t.y), pack_bf2(t.z, t.w));
            *(uint2*)(bb + 8192 + so) = make_uint2(pack_bf2(t.x - h0, t.y - h1),
                                                   pack_bf2(t.z - h2, t.w - h3));
        }
    };

    float acc[4][4] = {};
    int a_row_l = lane & 15;
    int a_cb_l  = (lane >> 4) << 4;

    issueV(0, 0);
    loadA(0);
    __syncthreads();
    xformA(0, 0);

    for (int kc = 0; kc < 32; kc++) {
        CP_WAIT0();
        __syncthreads();
        int nb = (kc + 1) & 1;
        if (kc + 1 < 32) {
            issueV(kc + 1, nb);
            loadA(kc + 1);
        }

        uint32_t bb = base + (uint32_t)(kc & 1) * AV_BUF;
        uint32_t aAh = bb, aAl = bb + 8192, aVh = bb + 16384, aVl = bb + 24576;

        #pragma unroll
        for (int ks = 0; ks < 4; ks++) {
            uint32_t a[4], al[4], bh2[4][2], bl2[4][2];
            {
                int row = wm * 16 + a_row_l;
                uint32_t off = sw128((uint32_t)(row * 128 + ks * 32 + a_cb_l));
                LDSM_X4(a[0], a[1], a[2], a[3], aAh + off);
                LDSM_X4(al[0], al[1], al[2], al[3], aAl + off);
            }
            #pragma unroll
            for (int nf = 0; nf < 4; nf++) {
                int row = ks * 16 + (lane & 15);
                uint32_t boff = sw128((uint32_t)(row * 128 + wn * 64 + nf * 16));
                LDSM_X2T(bh2[nf][0], bh2[nf][1], aVh + boff);
                LDSM_X2T(bl2[nf][0], bl2[nf][1], aVl + boff);
            }
            #pragma unroll
            for (int nf = 0; nf < 4; nf++) {
                MMA16816(acc[nf], a, bh2[nf]);
                MMA16816(acc[nf], a, bl2[nf]);
                MMA16816(acc[nf], al, bh2[nf]);
            }
        }

        if (kc + 1 < 32) xformA(kc + 1, nb);
        __syncthreads();
    }

    int b = bh >> 4, h = bh & 15;
    int r0 = lane >> 2;
    int c0 = (lane & 3) * 2;

    #pragma unroll
    for (int e2 = 0; e2 < 2; e2++) {
        int q = q0 + wm * 16 + r0 + e2 * 8;
        #pragma unroll
        for (int nf = 0; nf < 4; nf++) {
            int hd = wn * 32 + nf * 8 + c0;
            float v0 = acc[nf][e2*2+0];
            float v1 = acc[nf][e2*2+1];
            float h0 = __bfloat162float(__float2bfloat16(v0));
            float h1 = __bfloat162float(__float2bfloat16(v1));
            size_t idx = ((size_t)(b * L_ + q)) * D_ + h * HD_ + hd;
            *(uint32_t*)(g_xh + idx) = pack_bf2(v0, v1);
            *(uint32_t*)(g_xl + idx) = pack_bf2(v0 - h0, v1 - h1);
        }
    }
}

// ---------------------------------------------------------------------------
extern "C" void kernel_launch(void* const* d_in, const int* in_sizes, int n_in,
                              void* d_out, int out_size)
{
    const float* query = (const float*)d_in[0];
    const float* abias = (const float*)d_in[1];
    const float* Wq    = (const float*)d_in[2];
    const float* bq    = (const float*)d_in[3];
    const float* Wk    = (const float*)d_in[4];
    const float* bk    = (const float*)d_in[5];
    const float* Wv    = (const float*)d_in[6];
    const float* bv    = (const float*)d_in[7];
    const float* Wo    = (const float*)d_in[8];
    const float* bo    = (const float*)d_in[9];

    float* out  = (float*)d_out;
    float* ans  = out;
    float* attn = out + (size_t)M_ * D_;

    cudaFuncSetAttribute(logits_mma, cudaFuncAttributeMaxDynamicSharedMemorySize, LG_SMEM);
    cudaFuncSetAttribute(qkv_mma,    cudaFuncAttributeMaxDynamicSharedMemorySize, PJ_SMEM);
    cudaFuncSetAttribute(oproj_mma,  cudaFuncAttributeMaxDynamicSharedMemorySize, PJ_SMEM);
    cudaFuncSetAttribute(av_fused,   cudaFuncAttributeMaxDynamicSharedMemorySize, AV_SMEM);

    __nv_bfloat16 *p_inh, *p_inl, *p_wth, *p_wtl, *p_xh, *p_xl;
    cudaGetSymbolAddress((void**)&p_inh, g_inh);
    cudaGetSymbolAddress((void**)&p_inl, g_inl);
    cudaGetSymbolAddress((void**)&p_wth, g_wth);
    cudaGetSymbolAddress((void**)&p_wtl, g_wtl);
    cudaGetSymbolAddress((void**)&p_xh, g_xh);
    cudaGetSymbolAddress((void**)&p_xl, g_xl);

    split_x<<<M_ * D_ / 1024, 256>>>(query);
    split_wt<<<dim3(D_ / 64, D_ / 64, 4), 256>>>(Wq, Wk, Wv, Wo);

    qkv_mma<<<dim3(D_ / 64, M_ / 128, 3), 256, PJ_SMEM>>>(
        p_inh, p_inl, p_wth, p_wtl, bq, bk, bv);

    logits_mma<<<dim3(L_ / 64, L_ / 128, NBH), 256, LG_SMEM>>>(abias, attn);

    av_fused<<<dim3(L_ / 64, B_ * H_), 256, AV_SMEM>>>(attn);

    oproj_mma<<<dim3(D_ / 64, M_ / 128), 256, PJ_SMEM>>>(
        p_xh, p_xl, p_wth + 3 * (size_t)D_ * D_, p_wtl + 3 * (size_t)D_ * D_, bo, ans);
}

// round 16
// speedup vs baseline: 1.0679x; 1.0679x over previous
#include <cuda_runtime.h>
#include <cuda_bf16.h>
#include <cstdint>

#define B_  2
#define L_  2048
#define D_  1024
#define H_  16
#define HD_ 64
#define M_  (B_ * L_)
#define NBH (B_ * H_)   // 32
#define KT_ (L_ / 64)   // 32 k-tiles per row in logits (64-col tiles)

// ---------------------------------------------------------------------------
// Scratch (device globals)
// ---------------------------------------------------------------------------
__device__ __nv_bfloat16 g_inh[M_ * D_], g_inl[M_ * D_];
__device__ __nv_bfloat16 g_wth[4][D_ * D_], g_wtl[4][D_ * D_];
__device__ __nv_bfloat16 g_qh[B_ * H_ * L_ * HD_], g_ql[B_ * H_ * L_ * HD_];
__device__ __nv_bfloat16 g_kh[B_ * H_ * L_ * HD_], g_kl[B_ * H_ * L_ * HD_];
__device__ __nv_bfloat16 g_vh[B_ * H_ * L_ * HD_], g_vl[B_ * H_ * L_ * HD_];
__device__ __nv_bfloat16 g_xh[M_ * D_], g_xl[M_ * D_];
__device__ float g_psum[NBH * L_ * KT_];   // UNSHIFTED per-tile sum of exp(v)

__device__ __forceinline__ uint32_t smem_u32(const void* p) {
    uint32_t a;
    asm("{ .reg .u64 t; cvta.to.shared.u64 t, %1; cvt.u32.u64 %0, t; }"
        : "=r"(a) : "l"(p));
    return a;
}

__device__ __forceinline__ uint32_t sw128(uint32_t off) {
    return off ^ ((off >> 3) & 0x70);
}

__device__ __forceinline__ uint32_t pack_bf2(float a, float b) {
    return (uint32_t)__bfloat16_as_ushort(__float2bfloat16(a))
         | ((uint32_t)__bfloat16_as_ushort(__float2bfloat16(b)) << 16);
}

#define LDSM_X4(r0,r1,r2,r3,addr) \
    asm volatile("ldmatrix.sync.aligned.m8n8.x4.shared.b16 {%0,%1,%2,%3}, [%4];" \
        : "=r"(r0), "=r"(r1), "=r"(r2), "=r"(r3) : "r"(addr))

#define LDSM_X2(r0,r1,addr) \
    asm volatile("ldmatrix.sync.aligned.m8n8.x2.shared.b16 {%0,%1}, [%2];" \
        : "=r"(r0), "=r"(r1) : "r"(addr))

#define LDSM_X2T(r0,r1,addr) \
    asm volatile("ldmatrix.sync.aligned.m8n8.x2.trans.shared.b16 {%0,%1}, [%2];" \
        : "=r"(r0), "=r"(r1) : "r"(addr))

#define MMA16816(acc, af, bf) \
    asm volatile("mma.sync.aligned.m16n8k16.row.col.f32.bf16.bf16.f32 " \
        "{%0,%1,%2,%3}, {%4,%5,%6,%7}, {%8,%9}, {%0,%1,%2,%3};" \
        : "+f"((acc)[0]), "+f"((acc)[1]), "+f"((acc)[2]), "+f"((acc)[3]) \
        : "r"((af)[0]), "r"((af)[1]), "r"((af)[2]), "r"((af)[3]), \
          "r"((bf)[0]), "r"((bf)[1]))

#define CP16(dst_u32, src_ptr) \
    asm volatile("cp.async.cg.shared.global [%0], [%1], 16;" \
        :: "r"(dst_u32), "l"(src_ptr))
#define CP_COMMIT() asm volatile("cp.async.commit_group;" ::: "memory")
#define CP_WAIT0()  asm volatile("cp.async.wait_group 0;" ::: "memory")
#define CP_WAIT1()  asm volatile("cp.async.wait_group 1;" ::: "memory")

// ---------------------------------------------------------------------------
// Prep kernels
// ---------------------------------------------------------------------------
__global__ void split_x(const float* __restrict__ X)
{
    int i = (blockIdx.x * 256 + threadIdx.x) * 4;
    float4 v = *(const float4*)(X + i);
    float h0 = __bfloat162float(__float2bfloat16(v.x));
    float h1 = __bfloat162float(__float2bfloat16(v.y));
    float h2 = __bfloat162float(__float2bfloat16(v.z));
    float h3 = __bfloat162float(__float2bfloat16(v.w));
    *(uint2*)(g_inh + i) = make_uint2(pack_bf2(v.x, v.y), pack_bf2(v.z, v.w));
    *(uint2*)(g_inl + i) = make_uint2(pack_bf2(v.x - h0, v.y - h1), pack_bf2(v.z - h2, v.w - h3));
}

__global__ void split_wt(const float* __restrict__ W0, const float* __restrict__ W1,
                         const float* __restrict__ W2, const float* __restrict__ W3)
{
    __shared__ float ts[64][65];
    int widx = blockIdx.z;
    const float* W = (widx == 0) ? W0 : (widx == 1) ? W1 : (widx == 2) ? W2 : W3;
    int tid = threadIdx.x;
    int r0 = blockIdx.x * 64;
    int c0 = blockIdx.y * 64;

    #pragma unroll
    for (int i = 0; i < 4; i++) {
        int u = tid + i * 256;
        int row = u >> 4, c4 = (u & 15) * 4;
        float4 v = *(const float4*)(W + (size_t)(r0 + row) * D_ + c0 + c4);
        ts[row][c4+0] = v.x; ts[row][c4+1] = v.y;
        ts[row][c4+2] = v.z; ts[row][c4+3] = v.w;
    }
    __syncthreads();

    __nv_bfloat16* dh = g_wth[widx];
    __nv_bfloat16* dl = g_wtl[widx];
    #pragma unroll
    for (int i = 0; i < 4; i++) {
        int u = tid + i * 256;
        int nrow = u >> 4, k4 = (u & 15) * 4;
        float v0 = ts[k4+0][nrow], v1 = ts[k4+1][nrow];
        float v2 = ts[k4+2][nrow], v3 = ts[k4+3][nrow];
        float h0 = __bfloat162float(__float2bfloat16(v0));
        float h1 = __bfloat162float(__float2bfloat16(v1));
        float h2 = __bfloat162float(__float2bfloat16(v2));
        float h3 = __bfloat162float(__float2bfloat16(v3));
        size_t off = (size_t)(c0 + nrow) * D_ + r0 + k4;
        *(uint2*)(dh + off) = make_uint2(pack_bf2(v0, v1), pack_bf2(v2, v3));
        *(uint2*)(dl + off) = make_uint2(pack_bf2(v0-h0, v1-h1), pack_bf2(v2-h2, v3-h3));
    }
}

// ---------------------------------------------------------------------------
// Shared projection body (R13 shape: 128x128 tile, 64KB double buffers)
// ---------------------------------------------------------------------------
#define PJ_BUF  65536
#define PJ_SMEM (2 * PJ_BUF + 1024)

__device__ __forceinline__ void proj_body(
    char* smem_raw,
    const __nv_bfloat16* __restrict__ Xh, const __nv_bfloat16* __restrict__ Xl,
    const __nv_bfloat16* __restrict__ Wth, const __nv_bfloat16* __restrict__ Wtl,
    const float* __restrict__ bias, float* __restrict__ Yout,
    int mode, int n0, int m0)
{
    uint32_t raw = smem_u32(smem_raw);
    uint32_t base = (raw + 1023u) & ~1023u;

    int tid = threadIdx.x;
    int wid = tid >> 5, lane = tid & 31;
    int wm = wid >> 2, wn = wid & 3;

    float acc[4][4][4] = {};

    int a_row_l = lane & 15;
    int a_cb_l  = (lane >> 4) << 4;

    auto stage = [&](int kc, int buf) {
        uint32_t bb = base + (uint32_t)buf * PJ_BUF;
        int k0 = kc * 64;
        #pragma unroll
        for (int i = 0; i < 4; i++) {
            int u = tid + i * 256;
            int row = u >> 3, unit = u & 7;
            uint32_t dst = sw128((uint32_t)(row * 128 + unit * 16));
            size_t xoff = (size_t)(m0 + row) * D_ + k0 + unit * 8;
            size_t woff = (size_t)(n0 + row) * D_ + k0 + unit * 8;
            CP16(bb + dst,          Xh  + xoff);
            CP16(bb + 16384 + dst,  Xl  + xoff);
            CP16(bb + 32768 + dst,  Wth + woff);
            CP16(bb + 49152 + dst,  Wtl + woff);
        }
        CP_COMMIT();
    };

    stage(0, 0);

    for (int kc = 0; kc < 16; kc++) {
        CP_WAIT0();
        __syncthreads();
        if (kc + 1 < 16) stage(kc + 1, (kc + 1) & 1);

        uint32_t bb = base + (uint32_t)(kc & 1) * PJ_BUF;
        uint32_t aXh = bb, aXl = bb + 16384, aWh = bb + 32768, aWl = bb + 49152;

        #pragma unroll
        for (int ks = 0; ks < 4; ks++) {
            uint32_t a[4][4], bh[4][2], bl[4][2];
            #pragma unroll
            for (int mf = 0; mf < 4; mf++) {
                int row = wm * 64 + mf * 16 + a_row_l;
                uint32_t addr = aXh + sw128((uint32_t)(row * 128 + ks * 32 + a_cb_l));
                LDSM_X4(a[mf][0], a[mf][1], a[mf][2], a[mf][3], addr);
            }
            #pragma unroll
            for (int nf = 0; nf < 4; nf++) {
                int row = wn * 32 + nf * 8 + (lane & 7);
                uint32_t boff = sw128((uint32_t)(row * 128 + ks * 32 + (((lane >> 3) & 1) << 4)));
                LDSM_X2(bh[nf][0], bh[nf][1], aWh + boff);
                LDSM_X2(bl[nf][0], bl[nf][1], aWl + boff);
            }
            #pragma unroll
            for (int mf = 0; mf < 4; mf++)
                #pragma unroll
                for (int nf = 0; nf < 4; nf++) {
                    MMA16816(acc[mf][nf], a[mf], bh[nf]);
                    MMA16816(acc[mf][nf], a[mf], bl[nf]);
                }
            #pragma unroll
            for (int mf = 0; mf < 4; mf++) {
                int row = wm * 64 + mf * 16 + a_row_l;
                uint32_t addr = aXl + sw128((uint32_t)(row * 128 + ks * 32 + a_cb_l));
                LDSM_X4(a[mf][0], a[mf][1], a[mf][2], a[mf][3], addr);
            }
            #pragma unroll
            for (int mf = 0; mf < 4; mf++)
                #pragma unroll
                for (int nf = 0; nf < 4; nf++)
                    MMA16816(acc[mf][nf], a[mf], bh[nf]);
        }
        __syncthreads();
    }

    int r0 = lane >> 2;
    int c0 = (lane & 3) * 2;
    __nv_bfloat16* dsth = (mode == 0) ? g_qh : (mode == 1) ? g_kh : g_vh;
    __nv_bfloat16* dstl = (mode == 0) ? g_ql : (mode == 1) ? g_kl : g_vl;

    #pragma unroll
    for (int mf = 0; mf < 4; mf++) {
        #pragma unroll
        for (int e2 = 0; e2 < 2; e2++) {
            int r = m0 + wm * 64 + mf * 16 + r0 + e2 * 8;
            #pragma unroll
            for (int nf = 0; nf < 4; nf++) {
                int c = n0 + wn * 32 + nf * 8 + c0;
                float v0 = acc[mf][nf][e2*2+0] + bias[c];
                float v1 = acc[mf][nf][e2*2+1] + bias[c+1];
                if (mode < 3) {
                    int b = r >> 11, l = r & 2047;
                    int h = c >> 6, hd = c & 63;
                    size_t idx = (((size_t)(b * H_ + h)) * L_ + l) * HD_ + hd;
                    float h0 = __bfloat162float(__float2bfloat16(v0));
                    float h1 = __bfloat162float(__float2bfloat16(v1));
                    *(uint32_t*)(dsth + idx) = pack_bf2(v0, v1);
                    *(uint32_t*)(dstl + idx) = pack_bf2(v0 - h0, v1 - h1);
                } else {
                    *(float2*)(Yout + (size_t)r * D_ + c) = make_float2(v0, v1);
                }
            }
        }
    }
}

__global__ void __launch_bounds__(256)
qkv_mma(const __nv_bfloat16* __restrict__ Xh, const __nv_bfloat16* __restrict__ Xl,
        const __nv_bfloat16* __restrict__ Whb, const __nv_bfloat16* __restrict__ Wlb,
        const float* __restrict__ bq, const float* __restrict__ bk,
        const float* __restrict__ bv)
{
    extern __shared__ char smem_raw[];
    int m = blockIdx.z;
    const float* bias = (m == 0) ? bq : (m == 1) ? bk : bv;
    proj_body(smem_raw, Xh, Xl,
              Whb + (size_t)m * D_ * D_, Wlb + (size_t)m * D_ * D_,
              bias, nullptr, m, blockIdx.x * 128, blockIdx.y * 128);
}

__global__ void __launch_bounds__(256)
oproj_mma(const __nv_bfloat16* __restrict__ Xh, const __nv_bfloat16* __restrict__ Xl,
          const __nv_bfloat16* __restrict__ Wth, const __nv_bfloat16* __restrict__ Wtl,
          const float* __restrict__ bias, float* __restrict__ Yout)
{
    extern __shared__ char smem_raw[];
    proj_body(smem_raw, Xh, Xl, Wth, Wtl, bias, Yout, 3,
              blockIdx.x * 128, blockIdx.y * 128);
}

// ---------------------------------------------------------------------------
// Logits: 128q x 64k tiles, 2 CTAs/SM, hidden bias prefetch.
// Epilogue: bias add + attn write + UNSHIFTED sum(exp) only (no row max).
// ---------------------------------------------------------------------------
#define LGQH  0
#define LGQL  16384
#define LGKH  32768
#define LGKL  40960
#define LGB_OFF 49152
#define LGB_ROW 272                        // 64 f32 + 16B pad
#define LG_SMEM (LGB_OFF + 128 * LGB_ROW + 1024)   // ~84.5 KB

__global__ void __launch_bounds__(256, 2)
logits_mma(const float* __restrict__ abias, float* __restrict__ attn)
{
    extern __shared__ char smem_raw[];
    uint32_t raw = smem_u32(smem_raw);
    uint32_t base = (raw + 1023u) & ~1023u;
    char* smem = smem_raw + (base - raw);

    int tid  = threadIdx.x;
    int wid  = tid >> 5;
    int lane = tid & 31;
    int bh = blockIdx.z;
    int q0 = blockIdx.y * 128;
    int k0 = blockIdx.x * 64;
    int b  = bh >> 4;

    {
        const char* sQh = (const char*)(g_qh + ((size_t)bh * L_ + q0) * HD_);
        const char* sQl = (const char*)(g_ql + ((size_t)bh * L_ + q0) * HD_);
        const char* sKh = (const char*)(g_kh + ((size_t)bh * L_ + k0) * HD_);
        const char* sKl = (const char*)(g_kl + ((size_t)bh * L_ + k0) * HD_);
        #pragma unroll
        for (int u = 0; u < 4; u++) {
            uint32_t off = (uint32_t)(tid + u * 256) * 16u;
            uint32_t sw = sw128(off);
            CP16(base + LGQH + sw, sQh + off);
            CP16(base + LGQL + sw, sQl + off);
        }
        #pragma unroll
        for (int u = 0; u < 2; u++) {
            uint32_t off = (uint32_t)(tid + u * 256) * 16u;
            uint32_t sw = sw128(off);
            CP16(base + LGKH + sw, sKh + off);
            CP16(base + LGKL + sw, sKl + off);
        }
    }
    CP_COMMIT();
    #pragma unroll
    for (int i = 0; i < 8; i++) {
        int u = tid + i * 256;
        int row = u >> 4, unit = u & 15;
        CP16(base + LGB_OFF + row * LGB_ROW + unit * 16,
             abias + ((size_t)b * L_ + q0 + row) * L_ + k0 + unit * 4);
    }
    CP_COMMIT();

    CP_WAIT1();
    __syncthreads();

    int wm = wid >> 1;
    int wn = wid & 1;

    float acc[2][4][4] = {};

    int a_row_l = lane & 15;
    int a_cb_l  = (lane >> 4) << 4;
    int b_row_l = lane & 7;
    int b_cb_l  = ((lane >> 3) & 1) << 4;

    #pragma unroll
    for (int pass = 0; pass < 3; pass++) {
        uint32_t aBase = base + ((pass == 2) ? LGQL : LGQH);
        uint32_t bBase = base + ((pass == 1) ? LGKL : LGKH);

        #pragma unroll
        for (int ks = 0; ks < 4; ks++) {
            uint32_t a[2][4];
            #pragma unroll
            for (int mf = 0; mf < 2; mf++) {
                int row = wm * 32 + mf * 16 + a_row_l;
                uint32_t addr = aBase + sw128((uint32_t)(row * 128 + ks * 32 + a_cb_l));
                LDSM_X4(a[mf][0], a[mf][1], a[mf][2], a[mf][3], addr);
            }
            uint32_t bf[4][2];
            #pragma unroll
            for (int nf = 0; nf < 4; nf++) {
                int row = wn * 32 + nf * 8 + b_row_l;
                uint32_t addr = bBase + sw128((uint32_t)(row * 128 + ks * 32 + b_cb_l));
                LDSM_X2(bf[nf][0], bf[nf][1], addr);
            }
            #pragma unroll
            for (int mf = 0; mf < 2; mf++)
                #pragma unroll
                for (int nf = 0; nf < 4; nf++)
                    MMA16816(acc[mf][nf], a[mf], bf[nf]);
        }
    }

    CP_WAIT0();
    __syncthreads();

    float* ssum = (float*)smem;          // [128][2]
    const float* biasS = (const float*)(smem + LGB_OFF);

    size_t attn_base = (size_t)bh * L_ * L_;
    int r0 = lane >> 2;
    int c0 = (lane & 3) * 2;

    // fused: bias add + attn write + unshifted sum(exp)
    #pragma unroll
    for (int mf = 0; mf < 2; mf++) {
        #pragma unroll
        for (int e2 = 0; e2 < 2; e2++) {
            int rw = wm * 32 + mf * 16 + e2 * 8 + r0;
            const float* brow = biasS + rw * (LGB_ROW / 4);
            float* orow = attn + attn_base + (size_t)(q0 + rw) * L_ + k0;
            float s = 0.f;
            #pragma unroll
            for (int nf = 0; nf < 4; nf++) {
                int kl = wn * 32 + nf * 8 + c0;
                float v0 = acc[mf][nf][e2*2+0] * 0.125f + brow[kl];
                float v1 = acc[mf][nf][e2*2+1] * 0.125f + brow[kl+1];
                *(float2*)(orow + kl) = make_float2(v0, v1);
                s += __expf(v0) + __expf(v1);
            }
            s += __shfl_xor_sync(~0u, s, 1);
            s += __shfl_xor_sync(~0u, s, 2);
            if ((lane & 3) == 0) ssum[rw * 2 + wn] = s;
        }
    }
    __syncthreads();
    if (tid < 128) {
        float s = ssum[tid*2+0] + ssum[tid*2+1];
        size_t sidx = ((size_t)bh * L_ + q0 + tid) * KT_ + blockIdx.x;
        g_psum[sidx] = s;
    }
}

// ---------------------------------------------------------------------------
// av_fused: 64-q-row CTAs, 2 CTAs/SM. Inline unshifted-sum combine +
// double-buffered softmax-apply + P@V pipeline.
// ---------------------------------------------------------------------------
#define AV_BUF  32768
#define AV_SMEM (2 * AV_BUF + 1024)

__global__ void __launch_bounds__(256, 2)
av_fused(float* __restrict__ attn)
{
    extern __shared__ char smem_raw[];
    uint32_t raw = smem_u32(smem_raw);
    uint32_t base = (raw + 1023u) & ~1023u;
    char* smem = smem_raw + (base - raw);

    float* s_ri = (float*)(smem + 2 * AV_BUF);   // [64]

    int tid = threadIdx.x;
    int wid = tid >> 5, lane = tid & 31;
    int bh = blockIdx.y;
    int q0 = blockIdx.x * 64;
    int wm = wid >> 1;
    int wn = wid & 1;

    float* A = attn + (size_t)bh * L_ * L_;
    const __nv_bfloat16* Vh = g_vh + (size_t)bh * L_ * HD_;
    const __nv_bfloat16* Vl = g_vl + (size_t)bh * L_ * HD_;

    if (tid < 64) {
        size_t rowi = (size_t)bh * L_ + q0 + tid;
        const float* ps = g_psum + rowi * KT_;
        float S = 0.f;
        #pragma unroll 8
        for (int t = 0; t < KT_; t++) S += ps[t];
        s_ri[tid] = 1.0f / S;
    }

    int st_row[4], st_f4[4];
    #pragma unroll
    for (int i = 0; i < 4; i++) {
        int u = tid + i * 256;
        st_row[i] = u >> 4;
        st_f4[i]  = (u & 15) * 4;
    }

    auto issueV = [&](int kc, int buf) {
        uint32_t bb = base + (uint32_t)buf * AV_BUF;
        int k0 = kc * 64;
        #pragma unroll
        for (int i = 0; i < 2; i++) {
            int u = tid + i * 256;
            int row = u >> 3, unit = u & 7;
            uint32_t dst = sw128((uint32_t)(row * 128 + unit * 16));
            size_t off = (size_t)(k0 + row) * HD_ + unit * 8;
            CP16(bb + 16384 + dst, Vh + off);
            CP16(bb + 24576 + dst, Vl + off);
        }
        CP_COMMIT();
    };

    float4 apf[4];
    auto loadA = [&](int kc) {
        int k0 = kc * 64;
        #pragma unroll
        for (int i = 0; i < 4; i++)
            apf[i] = *(const float4*)(A + (size_t)(q0 + st_row[i]) * L_ + k0 + st_f4[i]);
    };

    auto xformA = [&](int kc, int buf) {
        char* bb = smem + buf * AV_BUF;
        int k0 = kc * 64;
        #pragma unroll
        for (int i = 0; i < 4; i++) {
            int row = st_row[i], f4 = st_f4[i];
            float ri = s_ri[row];
            float4 t = apf[i];
            t.x = __expf(t.x) * ri;
            t.y = __expf(t.y) * ri;
            t.z = __expf(t.z) * ri;
            t.w = __expf(t.w) * ri;
            *(float4*)(A + (size_t)(q0 + row) * L_ + k0 + f4) = t;
            float h0 = __bfloat162float(__float2bfloat16(t.x));
            float h1 = __bfloat162float(__float2bfloat16(t.y));
            float h2 = __bfloat162float(__float2bfloat16(t.z));
            float h3 = __bfloat162float(__float2bfloat16(t.w));
            uint32_t so = sw128((uint32_t)(row * 128 + f4 * 2));
            *(uint2*)(bb + so)        = make_uint2(pack_bf2(t.x, t.y), pack_bf2(t.z, t.w));
            *(uint2*)(bb + 8192 + so) = make_uint2(pack_bf2(t.x - h0, t.y - h1),
                                                   pack_bf2(t.z - h2, t.w - h3));
        }
    };

    float acc[4][4] = {};
    int a_row_l = lane & 15;
    int a_cb_l  = (lane >> 4) << 4;

    issueV(0, 0);
    loadA(0);
    __syncthreads();
    xformA(0, 0);

    for (int kc = 0; kc < 32; kc++) {
        CP_WAIT0();
        __syncthreads();
        int nb = (kc + 1) & 1;
        if (kc + 1 < 32) {
            issueV(kc + 1, nb);
            loadA(kc + 1);
        }

        uint32_t bb = base + (uint32_t)(kc & 1) * AV_BUF;
        uint32_t aAh = bb, aAl = bb + 8192, aVh = bb + 16384, aVl = bb + 24576;

        #pragma unroll
        for (int ks = 0; ks < 4; ks++) {
            uint32_t a[4], al[4], bh2[4][2], bl2[4][2];
            {
                int row = wm * 16 + a_row_l;
                uint32_t off = sw128((uint32_t)(row * 128 + ks * 32 + a_cb_l));
                LDSM_X4(a[0], a[1], a[2], a[3], aAh + off);
                LDSM_X4(al[0], al[1], al[2], al[3], aAl + off);
            }
            #pragma unroll
            for (int nf = 0; nf < 4; nf++) {
                int row = ks * 16 + (lane & 15);
                uint32_t boff = sw128((uint32_t)(row * 128 + wn * 64 + nf * 16));
                LDSM_X2T(bh2[nf][0], bh2[nf][1], aVh + boff);
                LDSM_X2T(bl2[nf][0], bl2[nf][1], aVl + boff);
            }
            #pragma unroll
            for (int nf = 0; nf < 4; nf++) {
                MMA16816(acc[nf], a, bh2[nf]);
                MMA16816(acc[nf], a, bl2[nf]);
                MMA16816(acc[nf], al, bh2[nf]);
            }
        }

        if (kc + 1 < 32) xformA(kc + 1, nb);
        __syncthreads();
    }

    int b = bh >> 4, h = bh & 15;
    int r0 = lane >> 2;
    int c0 = (lane & 3) * 2;

    #pragma unroll
    for (int e2 = 0; e2 < 2; e2++) {
        int q = q0 + wm * 16 + r0 + e2 * 8;
        #pragma unroll
        for (int nf = 0; nf < 4; nf++) {
            int hd = wn * 32 + nf * 8 + c0;
            float v0 = acc[nf][e2*2+0];
            float v1 = acc[nf][e2*2+1];
            float h0 = __bfloat162float(__float2bfloat16(v0));
            float h1 = __bfloat162float(__float2bfloat16(v1));
            size_t idx = ((size_t)(b * L_ + q)) * D_ + h * HD_ + hd;
            *(uint32_t*)(g_xh + idx) = pack_bf2(v0, v1);
            *(uint32_t*)(g_xl + idx) = pack_bf2(v0 - h0, v1 - h1);
        }
    }
}

// ---------------------------------------------------------------------------
extern "C" void kernel_launch(void* const* d_in, const int* in_sizes, int n_in,
                              void* d_out, int out_size)
{
    const float* query = (const float*)d_in[0];
    const float* abias = (const float*)d_in[1];
    const float* Wq    = (const float*)d_in[2];
    const float* bq    = (const float*)d_in[3];
    const float* Wk    = (const float*)d_in[4];
    const float* bk    = (const float*)d_in[5];
    const float* Wv    = (const float*)d_in[6];
    const float* bv    = (const float*)d_in[7];
    const float* Wo    = (const float*)d_in[8];
    const float* bo    = (const float*)d_in[9];

    float* out  = (float*)d_out;
    float* ans  = out;
    float* attn = out + (size_t)M_ * D_;

    cudaFuncSetAttribute(logits_mma, cudaFuncAttributeMaxDynamicSharedMemorySize, LG_SMEM);
    cudaFuncSetAttribute(qkv_mma,    cudaFuncAttributeMaxDynamicSharedMemorySize, PJ_SMEM);
    cudaFuncSetAttribute(oproj_mma,  cudaFuncAttributeMaxDynamicSharedMemorySize, PJ_SMEM);
    cudaFuncSetAttribute(av_fused,   cudaFuncAttributeMaxDynamicSharedMemorySize, AV_SMEM);

    __nv_bfloat16 *p_inh, *p_inl, *p_wth, *p_wtl, *p_xh, *p_xl;
    cudaGetSymbolAddress((void**)&p_inh, g_inh);
    cudaGetSymbolAddress((void**)&p_inl, g_inl);
    cudaGetSymbolAddress((void**)&p_wth, g_wth);
    cudaGetSymbolAddress((void**)&p_wtl, g_wtl);
    cudaGetSymbolAddress((void**)&p_xh, g_xh);
    cudaGetSymbolAddress((void**)&p_xl, g_xl);

    split_x<<<M_ * D_ / 1024, 256>>>(query);
    split_wt<<<dim3(D_ / 64, D_ / 64, 4), 256>>>(Wq, Wk, Wv, Wo);

    qkv_mma<<<dim3(D_ / 128, M_ / 128, 3), 256, PJ_SMEM>>>(
        p_inh, p_inl, p_wth, p_wtl, bq, bk, bv);

    logits_mma<<<dim3(L_ / 64, L_ / 128, NBH), 256, LG_SMEM>>>(abias, attn);

    av_fused<<<dim3(L_ / 64, B_ * H_), 256, AV_SMEM>>>(attn);

    oproj_mma<<<dim3(D_ / 128, M_ / 128), 256, PJ_SMEM>>>(
        p_xh, p_xl, p_wth + 3 * (size_t)D_ * D_, p_wtl + 3 * (size_t)D_ * D_, bo, ans);
}